// round 7
// baseline (speedup 1.0000x reference)
#include <cuda_runtime.h>

#define HH 128
#define WW 128
#define CC 16
#define FF 16
#define CF (CC * FF)
#define NB 2
#define SNX 32
#define SNY 32
#define GCTAS 128          // persistent grid: 2 x 8 x 8 ratio tiles, <= 148 SMs
#define APPLY_TILES (NB * 33 * 17)

// ratio[b][snx][sny][c*16+f] : 2 MB
__device__ float g_ratio[(size_t)NB * SNX * SNY * CF];
// monotonic device-wide barrier counter (never reset; ticket math handles replays)
__device__ unsigned g_bar;

__global__ __launch_bounds__(256) void fused_kernel(
    const float* __restrict__ pet, const float* __restrict__ bfeat,
    float* __restrict__ out)
{
    __shared__ float pet_s[20 * 20 * CC];   // 25.6 KB (reused as S2 later? no - separate)
    __shared__ float S2[2][CF];

    const int bid = blockIdx.x;             // 0..127
    const int t   = threadIdx.x;

    // ================= Phase 1: ratio for 4x4 patch tile =================
    {
        const int J  = bid & 7;
        const int I  = (bid >> 3) & 7;
        const int bz = bid >> 6;
        const int c  = t >> 4;
        const int r0 = 16 * I - 2;
        const int c0 = 16 * J - 2;

        for (int idx = t; idx < 20 * 20 * CC; idx += 256) {
            int pix = idx >> 4, cc = idx & 15;
            int u = pix / 20, v = pix - u * 20;
            int r = r0 + u, col = c0 + v;
            float val = 0.f;
            if ((unsigned)r < HH && (unsigned)col < WW)
                val = pet[((bz * HH + r) * WW + col) * CC + cc];
            pet_s[idx] = val;
        }
        __syncthreads();

        float d[4][4]  = {};
        float kk[4][4] = {};
        const float* bb = bfeat + (size_t)bz * HH * WW * CF + t;

#pragma unroll
        for (int u = 0; u < 20; u++) {
            const int r = r0 + u;
            const bool rowok = (unsigned)r < HH;
            float rd[4] = {}, rk[4] = {};
#pragma unroll
            for (int v = 0; v < 20; v++) {
                const int col = c0 + v;
                float bv = 0.f;
                if (rowok && (unsigned)col < WW)
                    bv = __ldg(bb + (r * WW + col) * CF);
                float pv = pet_s[(u * 20 + v) * CC + c];
                float pb = pv * bv;
                const int q1 = v >> 2;
                if (q1 <= 3)     { rd[q1] += bv;     rk[q1] += pb; }
                if (q1 - 1 >= 0) { rd[q1 - 1] += bv; rk[q1 - 1] += pb; }
            }
            const int p1 = u >> 2;
            if (p1 <= 3) {
#pragma unroll
                for (int q = 0; q < 4; q++) { d[p1][q] += rd[q]; kk[p1][q] += rk[q]; }
            }
            if (p1 - 1 >= 0) {
#pragma unroll
                for (int q = 0; q < 4; q++) { d[p1 - 1][q] += rd[q]; kk[p1 - 1][q] += rk[q]; }
            }
        }

#pragma unroll
        for (int p = 0; p < 4; p++)
#pragma unroll
            for (int q = 0; q < 4; q++) {
                float rat = (d[p][q] != 0.f) ? (kk[p][q] / d[p][q]) : 0.f;
                int snx = 4 * I + p, sny = 4 * J + q;
                g_ratio[(((size_t)bz * SNX + snx) * SNY + sny) * CF + t] = rat;
            }
    }

    // ================= Device-wide barrier (replay-safe ticket) ==========
    __threadfence();            // release g_ratio writes
    __syncthreads();
    if (t == 0) {
        unsigned ticket = atomicAdd(&g_bar, 1u);
        unsigned target = (ticket / GCTAS + 1u) * GCTAS;
        unsigned v;
        do {
            asm volatile("ld.acquire.gpu.u32 %0, [%1];" : "=r"(v) : "l"(&g_bar));
        } while (v < target);
    }
    __syncthreads();

    // ================= Phase 2: apply (b now L2-resident) ================
    const int q   = t & 63;     // float4 slot within pixel
    const int pg  = t >> 6;     // x-row within tile
    const int c   = q >> 2;
    const int f4  = q & 3;
    const bool lead = ((q & 3) == 0);

    for (int idx = bid; idx < APPLY_TILES; idx += GCTAS) {
        const int a2_ = idx % 17;            // y-block pair 0..16
        const int rem = idx / 17;
        const int a   = rem % 33;            // x-block 0..32
        const int bz  = rem / 33;

        // S for the two y-blocks
#pragma unroll
        for (int s = 0; s < 2; s++) {
            int blk = 2 * a2_ + s;
            float acc = 0.f;
#pragma unroll
            for (int da = 0; da < 2; da++) {
                int snx = a - 1 + da;
                if ((unsigned)snx >= SNX) continue;
#pragma unroll
                for (int db = 0; db < 2; db++) {
                    int sny = blk - 1 + db;
                    if ((unsigned)sny >= SNY) continue;
                    acc += g_ratio[(((size_t)bz * SNX + snx) * SNY + sny) * CF + t];
                }
            }
            S2[s][t] = acc;
        }
        __syncthreads();

        const int x = 4 * a - 2 + pg;
        const bool okx = (unsigned)x < HH;
        const float* rowbase = bfeat + ((size_t)(bz * HH + x) * WW) * CF + q * 4;

        float4 bv[8];
#pragma unroll
        for (int m = 0; m < 8; m++) {
            int y = 8 * a2_ - 2 + m;
            bv[m] = make_float4(0.f, 0.f, 0.f, 0.f);
            if (okx && (unsigned)y < WW)
                bv[m] = __ldg((const float4*)(rowbase + (size_t)y * CF));
        }

#pragma unroll
        for (int m = 0; m < 8; m++) {
            int y = 8 * a2_ - 2 + m;
            const int s = m >> 2;
            const float4 sv = *(const float4*)(&S2[s][c * 16 + f4 * 4]);
            float dot = bv[m].x * sv.x + bv[m].y * sv.y + bv[m].z * sv.z + bv[m].w * sv.w;
            dot += __shfl_xor_sync(0xffffffffu, dot, 1);
            dot += __shfl_xor_sync(0xffffffffu, dot, 2);
            if (lead && okx && (unsigned)y < WW)
                out[((bz * HH + x) * WW + y) * CC + c] = 0.25f * dot;
        }
        __syncthreads();   // protect S2 before next iteration overwrites
    }
}

extern "C" void kernel_launch(void* const* d_in, const int* in_sizes, int n_in,
                              void* d_out, int out_size)
{
    // Input order per reference signature: mr (unused), pet, b, px, py, sx, sy
    const float* pet   = (const float*)d_in[1];
    const float* bfeat = (const float*)d_in[2];

    fused_kernel<<<GCTAS, 256>>>(pet, bfeat, (float*)d_out);
}

// round 8
// speedup vs baseline: 1.1912x; 1.1912x over previous
#include <cuda_runtime.h>

#define HH 128
#define WW 128
#define CC 16
#define FF 16
#define CF (CC * FF)
#define NB 2
#define SNX 32
#define SNY 32

// ratio[b][snx][sny][c*16+f] : 2 MB
__device__ float g_ratio[(size_t)NB * SNX * SNY * CF];

// ---------------------------------------------------------------------------
// Kernel 1: per 4x4 patch tile (snx = 4I..4I+3, sny = 4J..4J+3).
// Union extent: rows 16I-2..16I+17 (20), cols 16J-2..16J+17 (20).
// Thread t owns cf index t (c = t>>4): 32 window accumulators in registers.
// ---------------------------------------------------------------------------
__global__ __launch_bounds__(256) void ratio_kernel(
    const float* __restrict__ pet, const float* __restrict__ bfeat)
{
    __shared__ float pet_s[20 * 20 * CC];   // 25.6 KB

    const int J  = blockIdx.x;   // 0..7
    const int I  = blockIdx.y;   // 0..7
    const int bz = blockIdx.z;
    const int t  = threadIdx.x;
    const int c  = t >> 4;

    const int r0 = 16 * I - 2;
    const int c0 = 16 * J - 2;

    for (int idx = t; idx < 20 * 20 * CC; idx += 256) {
        int pix = idx >> 4, cc = idx & 15;
        int u = pix / 20, v = pix - u * 20;
        int r = r0 + u, col = c0 + v;
        float val = 0.f;
        if ((unsigned)r < HH && (unsigned)col < WW)
            val = pet[((bz * HH + r) * WW + col) * CC + cc];
        pet_s[idx] = val;
    }
    __syncthreads();

    float d[4][4]  = {};
    float kk[4][4] = {};
    const float* bb = bfeat + (size_t)bz * HH * WW * CF + t;

#pragma unroll
    for (int u = 0; u < 20; u++) {
        const int r = r0 + u;
        const bool rowok = (unsigned)r < HH;
        float rd[4] = {}, rk[4] = {};
#pragma unroll
        for (int v = 0; v < 20; v++) {
            const int col = c0 + v;
            float bv = 0.f;
            if (rowok && (unsigned)col < WW)
                bv = __ldg(bb + (r * WW + col) * CF);
            float pv = pet_s[(u * 20 + v) * CC + c];
            float pb = pv * bv;
            const int q1 = v >> 2;
            if (q1 <= 3)     { rd[q1] += bv;     rk[q1] += pb; }
            if (q1 - 1 >= 0) { rd[q1 - 1] += bv; rk[q1 - 1] += pb; }
        }
        const int p1 = u >> 2;
        if (p1 <= 3) {
#pragma unroll
            for (int q = 0; q < 4; q++) { d[p1][q] += rd[q]; kk[p1][q] += rk[q]; }
        }
        if (p1 - 1 >= 0) {
#pragma unroll
            for (int q = 0; q < 4; q++) { d[p1 - 1][q] += rd[q]; kk[p1 - 1][q] += rk[q]; }
        }
    }

#pragma unroll
    for (int p = 0; p < 4; p++)
#pragma unroll
        for (int q = 0; q < 4; q++) {
            float rat = (d[p][q] != 0.f) ? (kk[p][q] / d[p][q]) : 0.f;
            int snx = 4 * I + p, sny = 4 * J + q;
            g_ratio[(((size_t)bz * SNX + snx) * SNY + sny) * CF + t] = rat;
        }
}

// ---------------------------------------------------------------------------
// Kernel 2: out(x,y,c) = 0.25 * sum_f b[x,y,c,f] * S(c,f)
// b loads issued FIRST (independent of S) so both latency epochs overlap.
// ---------------------------------------------------------------------------
__global__ __launch_bounds__(256) void apply_kernel(
    const float* __restrict__ bfeat, float* __restrict__ out)
{
    __shared__ float S2[2][CF];   // natural layout [c*16 + f]

    const int A2 = blockIdx.x;   // 0..16 (y-block pair)
    const int a  = blockIdx.y;   // 0..32 (x-block)
    const int bz = blockIdx.z;
    const int t  = threadIdx.x;

    const int q  = t & 63;       // float4 slot within pixel
    const int pg = t >> 6;       // x-row within tile
    const int c  = q >> 2;
    const int f4 = q & 3;

    const int x = 4 * a - 2 + pg;
    const bool okx = (unsigned)x < HH;
    const float* rowbase = bfeat + ((size_t)(bz * HH + x) * WW) * CF + q * 4;

    // ---- issue all 8 independent b loads first ----
    float4 bv[8];
#pragma unroll
    for (int m = 0; m < 8; m++) {
        int y = 8 * A2 - 2 + m;
        bv[m] = make_float4(0.f, 0.f, 0.f, 0.f);
        if (okx && (unsigned)y < WW)
            bv[m] = __ldg((const float4*)(rowbase + (size_t)y * CF));
    }

    // ---- S for the two y-blocks (overlaps with b loads in flight) ----
#pragma unroll
    for (int s = 0; s < 2; s++) {
        int blk = 2 * A2 + s;
        float acc = 0.f;
#pragma unroll
        for (int da = 0; da < 2; da++) {
            int snx = a - 1 + da;
            if ((unsigned)snx >= SNX) continue;
#pragma unroll
            for (int db = 0; db < 2; db++) {
                int sny = blk - 1 + db;
                if ((unsigned)sny >= SNY) continue;
                acc += __ldg(&g_ratio[(((size_t)bz * SNX + snx) * SNY + sny) * CF + t]);
            }
        }
        S2[s][t] = acc;
    }
    __syncthreads();

    const bool lead = ((q & 3) == 0);
#pragma unroll
    for (int m = 0; m < 8; m++) {
        int y = 8 * A2 - 2 + m;
        const int s = m >> 2;
        const float4 sv = *(const float4*)(&S2[s][c * 16 + f4 * 4]);
        float dot = bv[m].x * sv.x + bv[m].y * sv.y + bv[m].z * sv.z + bv[m].w * sv.w;
        dot += __shfl_xor_sync(0xffffffffu, dot, 1);
        dot += __shfl_xor_sync(0xffffffffu, dot, 2);
        if (lead && okx && (unsigned)y < WW)
            out[((bz * HH + x) * WW + y) * CC + c] = 0.25f * dot;
    }
}

extern "C" void kernel_launch(void* const* d_in, const int* in_sizes, int n_in,
                              void* d_out, int out_size)
{
    // Input order per reference signature: mr (unused), pet, b, px, py, sx, sy
    const float* pet   = (const float*)d_in[1];
    const float* bfeat = (const float*)d_in[2];

    dim3 grid1(SNY / 4, SNX / 4, NB);        // 8 x 8 x 2 tiles
    ratio_kernel<<<grid1, 256>>>(pet, bfeat);

    dim3 grid2(17, 33, NB);                  // y-pairs x x-blocks
    apply_kernel<<<grid2, 256>>>(bfeat, (float*)d_out);
}